// round 8
// baseline (speedup 1.0000x reference)
#include <cuda_runtime.h>
#include <math.h>
#include <stdint.h>

#define NN   40000
#define NE   640000
#define FIN  64
#define FOUT 128
#define NP   12
#define FTOT 768
#define GC   512      /* 4*FOUT */
#define KTOT 192
#define BN   64       /* nodes per step CTA */

// ---------------- device scratch ----------------
__device__ float d_deg[NN];
__device__ float d_dinv[NN];
__device__ int   d_counts[NN];
__device__ int   d_cursor[NN];
__device__ int   d_offsets[NN + 1];
__device__ int   d_csr[NE];
__device__ float d_S[(size_t)NP * NN * FIN];   // [t][n][k] fp32
__device__ float d_H[NN * FOUT];
__device__ float d_C[NN * FOUT];
__device__ float d_W1[FIN * GC];               // folded W_x @ W_h_top
__device__ float d_W2[FOUT * GC];              // W_h_bottom
__device__ float d_bias[GC];
__device__ float d_probs[NP];

struct GateW {
    const float* wx[4];
    const float* bx[4];
    const float* wh[4];
    const float* bh[4];
    const float* att;
};

// ---------------- packed f32x2 helpers ----------------
__device__ __forceinline__ unsigned long long pk2(float x) {
    unsigned long long r;
    asm("mov.b64 %0, {%1, %1};" : "=l"(r) : "f"(x));
    return r;
}
__device__ __forceinline__ unsigned long long pack2(float lo, float hi) {
    unsigned long long r;
    asm("mov.b64 %0, {%1, %2};" : "=l"(r) : "f"(lo), "f"(hi));
    return r;
}
__device__ __forceinline__ unsigned long long f2fma(unsigned long long a,
                                                    unsigned long long b,
                                                    unsigned long long c) {
    unsigned long long d;
    asm("fma.rn.f32x2 %0, %1, %2, %3;" : "=l"(d) : "l"(a), "l"(b), "l"(c));
    return d;
}
__device__ __forceinline__ float2 up2(unsigned long long v) {
    float2 r;
    asm("mov.b64 {%0, %1}, %2;" : "=f"(r.x), "=f"(r.y) : "l"(v));
    return r;
}

// ---------------- async copy helpers ----------------
__device__ __forceinline__ uint32_t smem_u32(const void* p) {
    uint32_t a;
    asm("{ .reg .u64 t; cvta.to.shared.u64 t, %1; cvt.u32.u64 %0, t; }" : "=r"(a) : "l"(p));
    return a;
}
__device__ __forceinline__ void cp16(uint32_t dst, const void* src) {
    asm volatile("cp.async.cg.shared.global [%0], [%1], 16;" :: "r"(dst), "l"(src));
}
#define CP_COMMIT() asm volatile("cp.async.commit_group;" ::: "memory")
#define CP_WAIT(n)  asm volatile("cp.async.wait_group %0;" :: "n"(n) : "memory")

// ---------------- small kernels ----------------
__global__ void zero_kernel() {
    int i = blockIdx.x * blockDim.x + threadIdx.x;
    int stride = gridDim.x * blockDim.x;
    for (int idx = i; idx < NN * FOUT; idx += stride) { d_H[idx] = 0.f; d_C[idx] = 0.f; }
    for (int idx = i; idx < NN; idx += stride) { d_deg[idx] = 0.f; d_counts[idx] = 0; d_cursor[idx] = 0; }
}

__global__ void deg_kernel(const int* __restrict__ ei, const float* __restrict__ ew) {
    int i = blockIdx.x * blockDim.x + threadIdx.x;
    int stride = gridDim.x * blockDim.x;
    for (int e = i; e < NE; e += stride) {
        int c = ei[NE + e];
        atomicAdd(&d_deg[c], ew[e]);
        atomicAdd(&d_counts[c], 1);
    }
}

__global__ __launch_bounds__(1024) void scan_kernel() {
    int tid = threadIdx.x;
    for (int n = tid; n < NN; n += 1024)
        d_dinv[n] = rsqrtf(d_deg[n] + 1.0f);
    const int CH = 40;
    int base = tid * CH;
    int sum = 0;
#pragma unroll 4
    for (int i = 0; i < CH; i++) { int idx = base + i; if (idx < NN) sum += d_counts[idx]; }
    int lane = tid & 31, wid = tid >> 5;
    int v = sum;
#pragma unroll
    for (int o = 1; o < 32; o <<= 1) { int t = __shfl_up_sync(0xffffffffu, v, o); if (lane >= o) v += t; }
    __shared__ int wsum[32];
    if (lane == 31) wsum[wid] = v;
    __syncthreads();
    if (wid == 0) {
        int w = wsum[lane];
#pragma unroll
        for (int o = 1; o < 32; o <<= 1) { int t = __shfl_up_sync(0xffffffffu, w, o); if (lane >= o) w += t; }
        wsum[lane] = w;
    }
    __syncthreads();
    int excl = v - sum + (wid ? wsum[wid - 1] : 0);
    int run = excl;
#pragma unroll 4
    for (int i = 0; i < CH; i++) {
        int idx = base + i;
        if (idx < NN) { d_offsets[idx] = run; run += d_counts[idx]; }
    }
    if (tid == 1023) d_offsets[NN] = run;
}

__global__ void fill_kernel(const int* __restrict__ ei) {
    int i = blockIdx.x * blockDim.x + threadIdx.x;
    int stride = gridDim.x * blockDim.x;
    for (int e = i; e < NE; e += stride) {
        int c = ei[NE + e];
        int p = atomicAdd(&d_cursor[c], 1);
        d_csr[d_offsets[c] + p] = e;
    }
}

__global__ __launch_bounds__(512) void prep_kernel(GateW gw) {
    int b = blockIdx.x;
    int c = threadIdx.x;
    int g = c >> 7, j = c & 127;
    if (b < 64) {
        int k = b;
        const float* wx = gw.wx[g];
        const float* wh = gw.wh[g];
        float acc = 0.f;
#pragma unroll 8
        for (int m = 0; m < FOUT; m++) acc += wx[k * FOUT + m] * wh[m * FOUT + j];
        d_W1[k * GC + c] = acc;
    } else if (b < 192) {
        int k = b - 64;
        d_W2[k * GC + c] = gw.wh[g][(FOUT + k) * FOUT + j];
    } else {
        float acc = gw.bh[g][j];
        for (int m = 0; m < FOUT; m++) acc += gw.bx[g][m] * gw.wh[g][m * FOUT + j];
        d_bias[c] = acc;
        if (c == 0) {
            float a[NP], mx = -1e30f, s = 0.f;
            for (int t = 0; t < NP; t++) { a[t] = gw.att[t]; mx = fmaxf(mx, a[t]); }
            for (int t = 0; t < NP; t++) { a[t] = expf(a[t] - mx); s += a[t]; }
            for (int t = 0; t < NP; t++) d_probs[t] = a[t] / s;
        }
    }
}

__global__ __launch_bounds__(768) void spmm_kernel(const float* __restrict__ X,
                                                   const int* __restrict__ ei,
                                                   const float* __restrict__ ew) {
    __shared__ int   srow[64];
    __shared__ float snrm[64];
    __shared__ float sval[FTOT];
    int n = blockIdx.x;
    int tid = threadIdx.x;
    float dn = d_dinv[n];
    float acc = dn * dn * X[n * FTOT + tid];
    int beg = d_offsets[n], end = d_offsets[n + 1];
    for (int eb = beg; eb < end; eb += 64) {
        int cnt = min(64, end - eb);
        if (tid < cnt) {
            int e = d_csr[eb + tid];
            int r = ei[e];
            srow[tid] = r;
            snrm[tid] = d_dinv[r] * ew[e] * dn;
        }
        __syncthreads();
#pragma unroll 4
        for (int i = 0; i < cnt; i++)
            acc += snrm[i] * X[srow[i] * FTOT + tid];
        __syncthreads();
    }
    sval[tid] = acc;
    __syncthreads();
    int t = tid >> 6, f = tid & 63;
    d_S[(size_t)t * NN * FIN + (size_t)n * FIN + f] = sval[f * NP + t];
}

// ---------------- FFMA2 step kernel ----------------
// Grid: 625 CTAs. CTA: 64 nodes x all 512 cols, 512 threads.
// Thread tile: 8 nodes x 8 cols -> 32 f32x2 accs.
// K = 192 in 12 chunks of 16; A loads vectorized as LDS.128 per 4-kk subgroup
// (LDS phases/kk: B=128, A=32 -> 160 < 256 FMA cyc => FMA-bound).
#define SM_B     0
#define SM_A     65536
#define SMEM_TOT (65536 + 8192)

__device__ __forceinline__ void load_chunk(uint32_t sb, int buf, int c, int t,
                                           int node0, int tid) {
    if (tid < 256) {
        int row = tid >> 2, q = tid & 3;
        int node = node0 + row;
        const float* src = (c < 4)
            ? &d_S[(size_t)t * NN * FIN + (size_t)node * FIN + c * 16 + q * 4]
            : &d_H[(size_t)node * FOUT + (c - 4) * 16 + q * 4];
        cp16(sb + SM_A + buf * 4096 + row * 64 + q * 16, src);
    }
#pragma unroll
    for (int i = 0; i < 4; i++) {
        int op = tid + 512 * i;            // 0..2047
        int row = op >> 7, q = op & 127;   // row 0..15, q 0..127 (16B units)
        const float* src = (c < 4) ? &d_W1[(c * 16 + row) * GC + q * 4]
                                   : &d_W2[((c - 4) * 16 + row) * GC + q * 4];
        cp16(sb + SM_B + buf * 32768 + row * 2048 + q * 16, src);
    }
}

__global__ __launch_bounds__(512) void step_ffma_kernel(int t, float* __restrict__ Hacc) {
    extern __shared__ char smem[];
    uint32_t sb = smem_u32(smem);
    int tid = threadIdx.x;
    int tx = tid & 63;        // col group
    int ty = tid >> 6;        // node group (0..7)
    int node0 = blockIdx.x * BN;

    unsigned long long acc[8][4];
#pragma unroll
    for (int i = 0; i < 8; i++)
#pragma unroll
        for (int j = 0; j < 4; j++) acc[i][j] = 0ull;

    load_chunk(sb, 0, 0, t, node0, tid);
    CP_COMMIT();

    for (int c = 0; c < 12; c++) {
        if (c < 11) {
            load_chunk(sb, (c + 1) & 1, c + 1, t, node0, tid);
            CP_COMMIT();
            CP_WAIT(1);
        } else {
            CP_WAIT(0);
        }
        __syncthreads();

        const float4* Bf4 = (const float4*)(smem + SM_B + (c & 1) * 32768);
        const float4* Af4 = (const float4*)(smem + SM_A + (c & 1) * 4096);

#pragma unroll
        for (int kg = 0; kg < 4; kg++) {
            // vectorized A loads: 8 nodes x 4 kk (broadcast LDS.128)
            float4 av[8];
#pragma unroll
            for (int i = 0; i < 8; i++)
                av[i] = Af4[(ty * 8 + i) * 4 + kg];
#pragma unroll
            for (int k4 = 0; k4 < 4; k4++) {
                int kk = kg * 4 + k4;
                float4 b0 = Bf4[kk * 128 + tx];         // cols tx*4..+3
                float4 b1 = Bf4[kk * 128 + 64 + tx];    // cols 256+tx*4..+3
                unsigned long long bb0 = pack2(b0.x, b0.y);
                unsigned long long bb1 = pack2(b0.z, b0.w);
                unsigned long long bb2 = pack2(b1.x, b1.y);
                unsigned long long bb3 = pack2(b1.z, b1.w);
#pragma unroll
                for (int i = 0; i < 8; i++) {
                    float a = (k4 == 0) ? av[i].x : (k4 == 1) ? av[i].y
                            : (k4 == 2) ? av[i].z : av[i].w;
                    unsigned long long aa = pk2(a);
                    acc[i][0] = f2fma(aa, bb0, acc[i][0]);
                    acc[i][1] = f2fma(aa, bb1, acc[i][1]);
                    acc[i][2] = f2fma(aa, bb2, acc[i][2]);
                    acc[i][3] = f2fma(aa, bb3, acc[i][3]);
                }
            }
        }
        __syncthreads();
    }

    // ---- epilogue: two halves of 32 nodes, Z staged over B buffers ----
    float* Zf = (float*)smem;
    float p = d_probs[t];
    int nd = tid >> 4, j8 = (tid & 15) * 8;

#pragma unroll
    for (int h = 0; h < 2; h++) {
        if ((ty >> 2) == h) {
            int l0 = (ty & 3) * 8;
#pragma unroll
            for (int i = 0; i < 8; i++) {
                float2 z0 = up2(acc[i][0]), z1 = up2(acc[i][1]);
                float2 z2 = up2(acc[i][2]), z3 = up2(acc[i][3]);
                *(float4*)&Zf[(l0 + i) * 512 + tx * 4] = make_float4(z0.x, z0.y, z1.x, z1.y);
                *(float4*)&Zf[(l0 + i) * 512 + 256 + tx * 4] = make_float4(z2.x, z2.y, z3.x, z3.y);
            }
        }
        __syncthreads();

        {
            int node = node0 + h * 32 + nd;
            float hv[8], cv[8], av[8];
            int gbase = node * FOUT + j8;
#pragma unroll
            for (int u = 0; u < 8; u++) {
                int j = j8 + u;
                float zi = Zf[nd * 512 + j]       + d_bias[j];
                float zf = Zf[nd * 512 + 128 + j] + d_bias[128 + j];
                float zc = Zf[nd * 512 + 256 + j] + d_bias[256 + j];
                float zo = Zf[nd * 512 + 384 + j] + d_bias[384 + j];
                float I  = 1.f / (1.f + __expf(-zi));
                float F  = 1.f / (1.f + __expf(-zf));
                float Ct = 1.f - 2.f / (__expf(2.f * zc) + 1.f);
                float O  = 1.f / (1.f + __expf(-zo));
                float cn = F * d_C[gbase + u] + I * Ct;
                float hh = O * (1.f - 2.f / (__expf(2.f * cn) + 1.f));
                hv[u] = hh; cv[u] = cn;
                av[u] = (t == 0 ? 0.f : Hacc[gbase + u]) + p * hh;
            }
            *(float4*)&d_H[gbase]     = make_float4(hv[0], hv[1], hv[2], hv[3]);
            *(float4*)&d_H[gbase + 4] = make_float4(hv[4], hv[5], hv[6], hv[7]);
            *(float4*)&d_C[gbase]     = make_float4(cv[0], cv[1], cv[2], cv[3]);
            *(float4*)&d_C[gbase + 4] = make_float4(cv[4], cv[5], cv[6], cv[7]);
            *(float4*)&Hacc[gbase]     = make_float4(av[0], av[1], av[2], av[3]);
            *(float4*)&Hacc[gbase + 4] = make_float4(av[4], av[5], av[6], av[7]);
        }
        __syncthreads();
    }
}

// ---------------- launch ----------------
extern "C" void kernel_launch(void* const* d_in, const int* in_sizes, int n_in,
                              void* d_out, int out_size) {
    const float* X   = (const float*)d_in[0];
    const int*   ei  = (const int*)d_in[1];
    const float* ew  = (const float*)d_in[2];
    const float* att = (const float*)d_in[3];
    GateW gw;
    for (int g = 0; g < 4; g++) {
        gw.wx[g] = (const float*)d_in[4 + 4 * g];
        gw.bx[g] = (const float*)d_in[5 + 4 * g];
        gw.wh[g] = (const float*)d_in[6 + 4 * g];
        gw.bh[g] = (const float*)d_in[7 + 4 * g];
    }
    gw.att = att;
    float* out = (float*)d_out;

    cudaFuncSetAttribute(step_ffma_kernel, cudaFuncAttributeMaxDynamicSharedMemorySize, SMEM_TOT);

    zero_kernel<<<512, 256>>>();
    deg_kernel<<<640, 256>>>(ei, ew);
    scan_kernel<<<1, 1024>>>();
    fill_kernel<<<640, 256>>>(ei);
    prep_kernel<<<193, 512>>>(gw);
    spmm_kernel<<<NN, 768>>>(X, ei, ew);
    for (int t = 0; t < NP; t++)
        step_ffma_kernel<<<NN / BN, 512, SMEM_TOT>>>(t, out);
}

// round 11
// speedup vs baseline: 1.1606x; 1.1606x over previous
#include <cuda_runtime.h>
#include <math.h>
#include <stdint.h>

#define NN   40000
#define NE   640000
#define FIN  64
#define FOUT 128
#define NP   12
#define FTOT 768
#define GC   512      /* 4*FOUT */
#define KTOT 192
#define BN   32       /* nodes per step CTA */

// ---------------- device scratch ----------------
__device__ float d_deg[NN];
__device__ float d_dinv[NN];
__device__ int   d_counts[NN];
__device__ int   d_cursor[NN];
__device__ int   d_offsets[NN + 1];
__device__ int   d_csr[NE];
__device__ float d_S[(size_t)NP * NN * FIN];   // [t][n][k] fp32
__device__ float d_H[NN * FOUT];
__device__ float d_C[NN * FOUT];
__device__ float d_W1[FIN * GC];               // folded W_x @ W_h_top
__device__ float d_W2[FOUT * GC];              // W_h_bottom
__device__ float d_bias[GC];
__device__ float d_probs[NP];

struct GateW {
    const float* wx[4];
    const float* bx[4];
    const float* wh[4];
    const float* bh[4];
    const float* att;
};

// ---------------- packed f32x2 helpers ----------------
__device__ __forceinline__ unsigned long long pk2(float x) {
    unsigned long long r;
    asm("mov.b64 %0, {%1, %1};" : "=l"(r) : "f"(x));
    return r;
}
__device__ __forceinline__ unsigned long long pack2(float lo, float hi) {
    unsigned long long r;
    asm("mov.b64 %0, {%1, %2};" : "=l"(r) : "f"(lo), "f"(hi));
    return r;
}
__device__ __forceinline__ unsigned long long f2fma(unsigned long long a,
                                                    unsigned long long b,
                                                    unsigned long long c) {
    unsigned long long d;
    asm("fma.rn.f32x2 %0, %1, %2, %3;" : "=l"(d) : "l"(a), "l"(b), "l"(c));
    return d;
}
__device__ __forceinline__ float2 up2(unsigned long long v) {
    float2 r;
    asm("mov.b64 {%0, %1}, %2;" : "=f"(r.x), "=f"(r.y) : "l"(v));
    return r;
}

// ---------------- async copy helpers ----------------
__device__ __forceinline__ uint32_t smem_u32(const void* p) {
    uint32_t a;
    asm("{ .reg .u64 t; cvta.to.shared.u64 t, %1; cvt.u32.u64 %0, t; }" : "=r"(a) : "l"(p));
    return a;
}
__device__ __forceinline__ void cp16(uint32_t dst, const void* src) {
    asm volatile("cp.async.cg.shared.global [%0], [%1], 16;" :: "r"(dst), "l"(src));
}
#define CP_COMMIT() asm volatile("cp.async.commit_group;" ::: "memory")
#define CP_WAIT(n)  asm volatile("cp.async.wait_group %0;" :: "n"(n) : "memory")

// ---------------- small kernels ----------------
__global__ void zero_kernel() {
    int i = blockIdx.x * blockDim.x + threadIdx.x;
    int stride = gridDim.x * blockDim.x;
    for (int idx = i; idx < NN * FOUT; idx += stride) { d_H[idx] = 0.f; d_C[idx] = 0.f; }
    for (int idx = i; idx < NN; idx += stride) { d_deg[idx] = 0.f; d_counts[idx] = 0; d_cursor[idx] = 0; }
}

__global__ void deg_kernel(const int* __restrict__ ei, const float* __restrict__ ew) {
    int i = blockIdx.x * blockDim.x + threadIdx.x;
    int stride = gridDim.x * blockDim.x;
    for (int e = i; e < NE; e += stride) {
        int c = ei[NE + e];
        atomicAdd(&d_deg[c], ew[e]);
        atomicAdd(&d_counts[c], 1);
    }
}

__global__ __launch_bounds__(1024) void scan_kernel() {
    int tid = threadIdx.x;
    for (int n = tid; n < NN; n += 1024)
        d_dinv[n] = rsqrtf(d_deg[n] + 1.0f);
    const int CH = 40;
    int base = tid * CH;
    int sum = 0;
#pragma unroll 4
    for (int i = 0; i < CH; i++) { int idx = base + i; if (idx < NN) sum += d_counts[idx]; }
    int lane = tid & 31, wid = tid >> 5;
    int v = sum;
#pragma unroll
    for (int o = 1; o < 32; o <<= 1) { int t = __shfl_up_sync(0xffffffffu, v, o); if (lane >= o) v += t; }
    __shared__ int wsum[32];
    if (lane == 31) wsum[wid] = v;
    __syncthreads();
    if (wid == 0) {
        int w = wsum[lane];
#pragma unroll
        for (int o = 1; o < 32; o <<= 1) { int t = __shfl_up_sync(0xffffffffu, w, o); if (lane >= o) w += t; }
        wsum[lane] = w;
    }
    __syncthreads();
    int excl = v - sum + (wid ? wsum[wid - 1] : 0);
    int run = excl;
#pragma unroll 4
    for (int i = 0; i < CH; i++) {
        int idx = base + i;
        if (idx < NN) { d_offsets[idx] = run; run += d_counts[idx]; }
    }
    if (tid == 1023) d_offsets[NN] = run;
}

__global__ void fill_kernel(const int* __restrict__ ei) {
    int i = blockIdx.x * blockDim.x + threadIdx.x;
    int stride = gridDim.x * blockDim.x;
    for (int e = i; e < NE; e += stride) {
        int c = ei[NE + e];
        int p = atomicAdd(&d_cursor[c], 1);
        d_csr[d_offsets[c] + p] = e;
    }
}

__global__ __launch_bounds__(512) void prep_kernel(GateW gw) {
    int b = blockIdx.x;
    int c = threadIdx.x;
    int g = c >> 7, j = c & 127;
    if (b < 64) {
        int k = b;
        const float* wx = gw.wx[g];
        const float* wh = gw.wh[g];
        float acc = 0.f;
#pragma unroll 8
        for (int m = 0; m < FOUT; m++) acc += wx[k * FOUT + m] * wh[m * FOUT + j];
        d_W1[k * GC + c] = acc;
    } else if (b < 192) {
        int k = b - 64;
        d_W2[k * GC + c] = gw.wh[g][(FOUT + k) * FOUT + j];
    } else {
        float acc = gw.bh[g][j];
        for (int m = 0; m < FOUT; m++) acc += gw.bx[g][m] * gw.wh[g][m * FOUT + j];
        d_bias[c] = acc;
        if (c == 0) {
            float a[NP], mx = -1e30f, s = 0.f;
            for (int t = 0; t < NP; t++) { a[t] = gw.att[t]; mx = fmaxf(mx, a[t]); }
            for (int t = 0; t < NP; t++) { a[t] = expf(a[t] - mx); s += a[t]; }
            for (int t = 0; t < NP; t++) d_probs[t] = a[t] / s;
        }
    }
}

__global__ __launch_bounds__(768) void spmm_kernel(const float* __restrict__ X,
                                                   const int* __restrict__ ei,
                                                   const float* __restrict__ ew) {
    __shared__ int   srow[64];
    __shared__ float snrm[64];
    __shared__ float sval[FTOT];
    int n = blockIdx.x;
    int tid = threadIdx.x;
    float dn = d_dinv[n];
    float acc = dn * dn * X[n * FTOT + tid];
    int beg = d_offsets[n], end = d_offsets[n + 1];
    for (int eb = beg; eb < end; eb += 64) {
        int cnt = min(64, end - eb);
        if (tid < cnt) {
            int e = d_csr[eb + tid];
            int r = ei[e];
            srow[tid] = r;
            snrm[tid] = d_dinv[r] * ew[e] * dn;
        }
        __syncthreads();
#pragma unroll 4
        for (int i = 0; i < cnt; i++)
            acc += snrm[i] * X[srow[i] * FTOT + tid];
        __syncthreads();
    }
    sval[tid] = acc;
    __syncthreads();
    int t = tid >> 6, f = tid & 63;
    d_S[(size_t)t * NN * FIN + (size_t)n * FIN + f] = sval[f * NP + t];
}

// ---------------- FFMA2 step kernel (2 CTAs/SM) ----------------
// Grid: 1250 CTAs. CTA: 32 nodes x all 512 cols, 256 threads.
// Thread tile: 8 nodes x 8 cols -> 32 f32x2 accs.
// K = 192 in 12 chunks of 16, cp.async double-buffered.
// SMEM: B 2x32KB at [0,64K); A 2x2KB at [64K,68K). 68KB/CTA -> 2 CTA/SM.
// Epilogue: Z staged across full smem with padded stride 516 floats.
#define SM_B     0
#define SM_A     65536
#define SMEM_TOT (65536 + 4096)
#define ZSTRIDE  516

__device__ __forceinline__ void load_chunk(uint32_t sb, int buf, int c, int t,
                                           int node0, int tid) {
    if (tid < 128) {
        int row = tid >> 2, q = tid & 3;          // 32 rows x 4 quads
        int node = node0 + row;
        const float* src = (c < 4)
            ? &d_S[(size_t)t * NN * FIN + (size_t)node * FIN + c * 16 + q * 4]
            : &d_H[(size_t)node * FOUT + (c - 4) * 16 + q * 4];
        cp16(sb + SM_A + buf * 2048 + row * 64 + q * 16, src);
    }
#pragma unroll
    for (int i = 0; i < 8; i++) {
        int op = tid + 256 * i;            // 0..2047
        int row = op >> 7, q = op & 127;   // row 0..15, q 0..127 (16B units)
        const float* src = (c < 4) ? &d_W1[(c * 16 + row) * GC + q * 4]
                                   : &d_W2[((c - 4) * 16 + row) * GC + q * 4];
        cp16(sb + SM_B + buf * 32768 + row * 2048 + q * 16, src);
    }
}

__global__ __launch_bounds__(256, 2) void step_ffma_kernel(int t, float* __restrict__ Hacc) {
    extern __shared__ char smem[];
    uint32_t sb = smem_u32(smem);
    int tid = threadIdx.x;
    int tx = tid & 63;        // col group
    int ty = tid >> 6;        // node group (0..3)
    int node0 = blockIdx.x * BN;

    unsigned long long acc[8][4];
#pragma unroll
    for (int i = 0; i < 8; i++)
#pragma unroll
        for (int j = 0; j < 4; j++) acc[i][j] = 0ull;

    load_chunk(sb, 0, 0, t, node0, tid);
    CP_COMMIT();

    for (int c = 0; c < 12; c++) {
        if (c < 11) {
            load_chunk(sb, (c + 1) & 1, c + 1, t, node0, tid);
            CP_COMMIT();
            CP_WAIT(1);
        } else {
            CP_WAIT(0);
        }
        __syncthreads();

        const float4* Bf4 = (const float4*)(smem + SM_B + (c & 1) * 32768);
        const float2* Af2 = (const float2*)(smem + SM_A + (c & 1) * 2048);

#pragma unroll
        for (int kg = 0; kg < 8; kg++) {
            // A: 8 nodes x 2 kk per group (broadcast LDS.64)
            float2 av[8];
#pragma unroll
            for (int i = 0; i < 8; i++)
                av[i] = Af2[(ty * 8 + i) * 8 + kg];
#pragma unroll
            for (int k2 = 0; k2 < 2; k2++) {
                int kk = kg * 2 + k2;
                float4 b0 = Bf4[kk * 128 + tx];         // cols tx*4..+3
                float4 b1 = Bf4[kk * 128 + 64 + tx];    // cols 256+tx*4..+3
                unsigned long long bb0 = pack2(b0.x, b0.y);
                unsigned long long bb1 = pack2(b0.z, b0.w);
                unsigned long long bb2 = pack2(b1.x, b1.y);
                unsigned long long bb3 = pack2(b1.z, b1.w);
#pragma unroll
                for (int i = 0; i < 8; i++) {
                    unsigned long long aa = pk2(k2 ? av[i].y : av[i].x);
                    acc[i][0] = f2fma(aa, bb0, acc[i][0]);
                    acc[i][1] = f2fma(aa, bb1, acc[i][1]);
                    acc[i][2] = f2fma(aa, bb2, acc[i][2]);
                    acc[i][3] = f2fma(aa, bb3, acc[i][3]);
                }
            }
        }
        __syncthreads();
    }

    // ---- stage all 32 nodes' Z over smem (stride 516 floats) ----
    float* Zf = (float*)smem;
#pragma unroll
    for (int i = 0; i < 8; i++) {
        float2 z0 = up2(acc[i][0]), z1 = up2(acc[i][1]);
        float2 z2 = up2(acc[i][2]), z3 = up2(acc[i][3]);
        int l = ty * 8 + i;
        *(float4*)&Zf[l * ZSTRIDE + tx * 4]       = make_float4(z0.x, z0.y, z1.x, z1.y);
        *(float4*)&Zf[l * ZSTRIDE + 256 + tx * 4] = make_float4(z2.x, z2.y, z3.x, z3.y);
    }
    __syncthreads();

    // ---- fused LSTM epilogue: thread -> node (tid>>3), 16 features ----
    {
        float p = d_probs[t];
        int nd = tid >> 3;
        int j0 = (tid & 7) * 16;
        int node = node0 + nd;
        int gbase = node * FOUT + j0;
#pragma unroll
        for (int q = 0; q < 4; q++) {
            float4 c4 = *(const float4*)&d_C[gbase + q * 4];
            float4 a4 = (t == 0) ? make_float4(0.f, 0.f, 0.f, 0.f)
                                 : *(const float4*)&Hacc[gbase + q * 4];
            float hv[4], cv[4], av4[4];
            const float* cold = &c4.x;
            const float* aold = &a4.x;
#pragma unroll
            for (int u = 0; u < 4; u++) {
                int j = j0 + q * 4 + u;
                float zi = Zf[nd * ZSTRIDE + j]       + d_bias[j];
                float zf = Zf[nd * ZSTRIDE + 128 + j] + d_bias[128 + j];
                float zc = Zf[nd * ZSTRIDE + 256 + j] + d_bias[256 + j];
                float zo = Zf[nd * ZSTRIDE + 384 + j] + d_bias[384 + j];
                float I  = 1.f / (1.f + __expf(-zi));
                float F  = 1.f / (1.f + __expf(-zf));
                float Ct = 1.f - 2.f / (__expf(2.f * zc) + 1.f);
                float O  = 1.f / (1.f + __expf(-zo));
                float cn = F * cold[u] + I * Ct;
                float hh = O * (1.f - 2.f / (__expf(2.f * cn) + 1.f));
                hv[u] = hh; cv[u] = cn; av4[u] = aold[u] + p * hh;
            }
            *(float4*)&d_H[gbase + q * 4]  = make_float4(hv[0], hv[1], hv[2], hv[3]);
            *(float4*)&d_C[gbase + q * 4]  = make_float4(cv[0], cv[1], cv[2], cv[3]);
            *(float4*)&Hacc[gbase + q * 4] = make_float4(av4[0], av4[1], av4[2], av4[3]);
        }
    }
}

// ---------------- launch ----------------
extern "C" void kernel_launch(void* const* d_in, const int* in_sizes, int n_in,
                              void* d_out, int out_size) {
    const float* X   = (const float*)d_in[0];
    const int*   ei  = (const int*)d_in[1];
    const float* ew  = (const float*)d_in[2];
    const float* att = (const float*)d_in[3];
    GateW gw;
    for (int g = 0; g < 4; g++) {
        gw.wx[g] = (const float*)d_in[4 + 4 * g];
        gw.bx[g] = (const float*)d_in[5 + 4 * g];
        gw.wh[g] = (const float*)d_in[6 + 4 * g];
        gw.bh[g] = (const float*)d_in[7 + 4 * g];
    }
    gw.att = att;
    float* out = (float*)d_out;

    cudaFuncSetAttribute(step_ffma_kernel, cudaFuncAttributeMaxDynamicSharedMemorySize, SMEM_TOT);

    zero_kernel<<<512, 256>>>();
    deg_kernel<<<640, 256>>>(ei, ew);
    scan_kernel<<<1, 1024>>>();
    fill_kernel<<<640, 256>>>(ei);
    prep_kernel<<<193, 512>>>(gw);
    spmm_kernel<<<NN, 768>>>(X, ei, ew);
    for (int t = 0; t < NP; t++)
        step_ffma_kernel<<<NN / BN, 256, SMEM_TOT>>>(t, out);
}

// round 12
// speedup vs baseline: 1.2498x; 1.0769x over previous
#include <cuda_runtime.h>
#include <math.h>
#include <stdint.h>

#define NN   40000
#define NE   640000
#define FIN  64
#define FOUT 128
#define NP   12
#define FTOT 768
#define GC   512      /* 4*FOUT */
#define KTOT 192
#define BN   32       /* nodes per step CTA */

// ---------------- device scratch ----------------
__device__ float d_deg[NN];
__device__ float d_dinv[NN];
__device__ int   d_counts[NN];
__device__ int   d_cursor[NN];
__device__ int   d_offsets[NN + 1];
__device__ int   d_csr[NE];       // source node per CSR slot
__device__ float d_csrw[NE];      // norm weight per CSR slot
__device__ float d_Xt[(size_t)NP * NN * FIN];  // X transposed [t][n][f]
__device__ float d_S[(size_t)NP * NN * FIN];   // [t][n][k] fp32
__device__ float d_H[NN * FOUT];
__device__ float d_C[NN * FOUT];
__device__ float d_W1[FIN * GC];               // folded W_x @ W_h_top
__device__ float d_W2[FOUT * GC];              // W_h_bottom
__device__ float d_bias[GC];
__device__ float d_probs[NP];

struct GateW {
    const float* wx[4];
    const float* bx[4];
    const float* wh[4];
    const float* bh[4];
    const float* att;
};

// ---------------- packed f32x2 helpers ----------------
__device__ __forceinline__ unsigned long long pk2(float x) {
    unsigned long long r;
    asm("mov.b64 %0, {%1, %1};" : "=l"(r) : "f"(x));
    return r;
}
__device__ __forceinline__ unsigned long long pack2(float lo, float hi) {
    unsigned long long r;
    asm("mov.b64 %0, {%1, %2};" : "=l"(r) : "f"(lo), "f"(hi));
    return r;
}
__device__ __forceinline__ unsigned long long f2fma(unsigned long long a,
                                                    unsigned long long b,
                                                    unsigned long long c) {
    unsigned long long d;
    asm("fma.rn.f32x2 %0, %1, %2, %3;" : "=l"(d) : "l"(a), "l"(b), "l"(c));
    return d;
}
__device__ __forceinline__ float2 up2(unsigned long long v) {
    float2 r;
    asm("mov.b64 {%0, %1}, %2;" : "=f"(r.x), "=f"(r.y) : "l"(v));
    return r;
}

// ---------------- async copy helpers ----------------
__device__ __forceinline__ uint32_t smem_u32(const void* p) {
    uint32_t a;
    asm("{ .reg .u64 t; cvta.to.shared.u64 t, %1; cvt.u32.u64 %0, t; }" : "=r"(a) : "l"(p));
    return a;
}
__device__ __forceinline__ void cp16(uint32_t dst, const void* src) {
    asm volatile("cp.async.cg.shared.global [%0], [%1], 16;" :: "r"(dst), "l"(src));
}
#define CP_COMMIT() asm volatile("cp.async.commit_group;" ::: "memory")
#define CP_WAIT(n)  asm volatile("cp.async.wait_group %0;" :: "n"(n) : "memory")

// ---------------- small kernels ----------------
__global__ void zero_kernel() {
    int i = blockIdx.x * blockDim.x + threadIdx.x;
    int stride = gridDim.x * blockDim.x;
    for (int idx = i; idx < NN * FOUT; idx += stride) { d_H[idx] = 0.f; d_C[idx] = 0.f; }
    for (int idx = i; idx < NN; idx += stride) { d_deg[idx] = 0.f; d_counts[idx] = 0; d_cursor[idx] = 0; }
}

__global__ void deg_kernel(const int* __restrict__ ei, const float* __restrict__ ew) {
    int i = blockIdx.x * blockDim.x + threadIdx.x;
    int stride = gridDim.x * blockDim.x;
    for (int e = i; e < NE; e += stride) {
        int c = ei[NE + e];
        atomicAdd(&d_deg[c], ew[e]);
        atomicAdd(&d_counts[c], 1);
    }
}

__global__ __launch_bounds__(1024) void scan_kernel() {
    int tid = threadIdx.x;
    for (int n = tid; n < NN; n += 1024)
        d_dinv[n] = rsqrtf(d_deg[n] + 1.0f);
    const int CH = 40;
    int base = tid * CH;
    int sum = 0;
#pragma unroll 4
    for (int i = 0; i < CH; i++) { int idx = base + i; if (idx < NN) sum += d_counts[idx]; }
    int lane = tid & 31, wid = tid >> 5;
    int v = sum;
#pragma unroll
    for (int o = 1; o < 32; o <<= 1) { int t = __shfl_up_sync(0xffffffffu, v, o); if (lane >= o) v += t; }
    __shared__ int wsum[32];
    if (lane == 31) wsum[wid] = v;
    __syncthreads();
    if (wid == 0) {
        int w = wsum[lane];
#pragma unroll
        for (int o = 1; o < 32; o <<= 1) { int t = __shfl_up_sync(0xffffffffu, w, o); if (lane >= o) w += t; }
        wsum[lane] = w;
    }
    __syncthreads();
    int excl = v - sum + (wid ? wsum[wid - 1] : 0);
    int run = excl;
#pragma unroll 4
    for (int i = 0; i < CH; i++) {
        int idx = base + i;
        if (idx < NN) { d_offsets[idx] = run; run += d_counts[idx]; }
    }
    if (tid == 1023) d_offsets[NN] = run;
}

// fill CSR with src index + precomputed norm weight (needs dinv -> after scan)
__global__ void fill_kernel(const int* __restrict__ ei, const float* __restrict__ ew) {
    int i = blockIdx.x * blockDim.x + threadIdx.x;
    int stride = gridDim.x * blockDim.x;
    for (int e = i; e < NE; e += stride) {
        int c = ei[NE + e];
        int r = ei[e];
        int p = atomicAdd(&d_cursor[c], 1);
        int slot = d_offsets[c] + p;
        d_csr[slot]  = r;
        d_csrw[slot] = d_dinv[r] * ew[e] * d_dinv[c];
    }
}

__global__ __launch_bounds__(512) void prep_kernel(GateW gw) {
    int b = blockIdx.x;
    int c = threadIdx.x;
    int g = c >> 7, j = c & 127;
    if (b < 64) {
        int k = b;
        const float* wx = gw.wx[g];
        const float* wh = gw.wh[g];
        float acc = 0.f;
#pragma unroll 8
        for (int m = 0; m < FOUT; m++) acc += wx[k * FOUT + m] * wh[m * FOUT + j];
        d_W1[k * GC + c] = acc;
    } else if (b < 192) {
        int k = b - 64;
        d_W2[k * GC + c] = gw.wh[g][(FOUT + k) * FOUT + j];
    } else {
        float acc = gw.bh[g][j];
        for (int m = 0; m < FOUT; m++) acc += gw.bx[g][m] * gw.wh[g][m * FOUT + j];
        d_bias[c] = acc;
        if (c == 0) {
            float a[NP], mx = -1e30f, s = 0.f;
            for (int t = 0; t < NP; t++) { a[t] = gw.att[t]; mx = fmaxf(mx, a[t]); }
            for (int t = 0; t < NP; t++) { a[t] = expf(a[t] - mx); s += a[t]; }
            for (int t = 0; t < NP; t++) d_probs[t] = a[t] / s;
        }
    }
}

// X [n][f][t] -> Xt [t][n][f]
__global__ __launch_bounds__(768) void transpose_kernel(const float* __restrict__ X) {
    __shared__ float sv[FTOT];
    int n = blockIdx.x;
    int tid = threadIdx.x;
    sv[tid] = X[(size_t)n * FTOT + tid];
    __syncthreads();
    int t = tid >> 6, f = tid & 63;
    d_Xt[((size_t)t * NN + n) * FIN + f] = sv[f * NP + t];
}

// per-period gather SpMM: S[t][n][f]; 4 nodes per 256-thread block
__global__ __launch_bounds__(256) void spmm_t_kernel(int t) {
    int nd = blockIdx.x * 4 + (threadIdx.x >> 6);
    int f = threadIdx.x & 63;
    const float* Xt = d_Xt + (size_t)t * NN * FIN;
    float dn = d_dinv[nd];
    float acc = dn * dn * Xt[(size_t)nd * FIN + f];
    int beg = d_offsets[nd], end = d_offsets[nd + 1];
    int e = beg;
    float acc2 = 0.f;
    for (; e + 1 < end; e += 2) {
        acc  += d_csrw[e]     * Xt[(size_t)d_csr[e] * FIN + f];
        acc2 += d_csrw[e + 1] * Xt[(size_t)d_csr[e + 1] * FIN + f];
    }
    if (e < end) acc += d_csrw[e] * Xt[(size_t)d_csr[e] * FIN + f];
    __stcs(&d_S[((size_t)t * NN + nd) * FIN + f], acc + acc2);
}

// ---------------- FFMA2 step kernel (2 CTAs/SM) ----------------
#define SM_B     0
#define SM_A     65536
#define SMEM_TOT (65536 + 4096)
#define ZSTRIDE  516

__device__ __forceinline__ void load_chunk(uint32_t sb, int buf, int c, int t,
                                           int node0, int tid) {
    if (tid < 128) {
        int row = tid >> 2, q = tid & 3;          // 32 rows x 4 quads
        int node = node0 + row;
        const float* src = (c < 4)
            ? &d_S[(size_t)t * NN * FIN + (size_t)node * FIN + c * 16 + q * 4]
            : &d_H[(size_t)node * FOUT + (c - 4) * 16 + q * 4];
        cp16(sb + SM_A + buf * 2048 + row * 64 + q * 16, src);
    }
#pragma unroll
    for (int i = 0; i < 8; i++) {
        int op = tid + 256 * i;            // 0..2047
        int row = op >> 7, q = op & 127;   // row 0..15, q 0..127 (16B units)
        const float* src = (c < 4) ? &d_W1[(c * 16 + row) * GC + q * 4]
                                   : &d_W2[((c - 4) * 16 + row) * GC + q * 4];
        cp16(sb + SM_B + buf * 32768 + row * 2048 + q * 16, src);
    }
}

__global__ __launch_bounds__(256, 2) void step_ffma_kernel(int t, float* __restrict__ Hacc) {
    extern __shared__ char smem[];
    uint32_t sb = smem_u32(smem);
    int tid = threadIdx.x;
    int tx = tid & 63;        // col group
    int ty = tid >> 6;        // node group (0..3)
    int node0 = blockIdx.x * BN;

    unsigned long long acc[8][4];
#pragma unroll
    for (int i = 0; i < 8; i++)
#pragma unroll
        for (int j = 0; j < 4; j++) acc[i][j] = 0ull;

    load_chunk(sb, 0, 0, t, node0, tid);
    CP_COMMIT();

    for (int c = 0; c < 12; c++) {
        if (c < 11) {
            load_chunk(sb, (c + 1) & 1, c + 1, t, node0, tid);
            CP_COMMIT();
            CP_WAIT(1);
        } else {
            CP_WAIT(0);
        }
        __syncthreads();

        const float4* Bf4 = (const float4*)(smem + SM_B + (c & 1) * 32768);
        const float2* Af2 = (const float2*)(smem + SM_A + (c & 1) * 2048);

#pragma unroll
        for (int kg = 0; kg < 8; kg++) {
            float2 av[8];
#pragma unroll
            for (int i = 0; i < 8; i++)
                av[i] = Af2[(ty * 8 + i) * 8 + kg];
#pragma unroll
            for (int k2 = 0; k2 < 2; k2++) {
                int kk = kg * 2 + k2;
                float4 b0 = Bf4[kk * 128 + tx];
                float4 b1 = Bf4[kk * 128 + 64 + tx];
                unsigned long long bb0 = pack2(b0.x, b0.y);
                unsigned long long bb1 = pack2(b0.z, b0.w);
                unsigned long long bb2 = pack2(b1.x, b1.y);
                unsigned long long bb3 = pack2(b1.z, b1.w);
#pragma unroll
                for (int i = 0; i < 8; i++) {
                    unsigned long long aa = pk2(k2 ? av[i].y : av[i].x);
                    acc[i][0] = f2fma(aa, bb0, acc[i][0]);
                    acc[i][1] = f2fma(aa, bb1, acc[i][1]);
                    acc[i][2] = f2fma(aa, bb2, acc[i][2]);
                    acc[i][3] = f2fma(aa, bb3, acc[i][3]);
                }
            }
        }
        __syncthreads();
    }

    float* Zf = (float*)smem;
#pragma unroll
    for (int i = 0; i < 8; i++) {
        float2 z0 = up2(acc[i][0]), z1 = up2(acc[i][1]);
        float2 z2 = up2(acc[i][2]), z3 = up2(acc[i][3]);
        int l = ty * 8 + i;
        *(float4*)&Zf[l * ZSTRIDE + tx * 4]       = make_float4(z0.x, z0.y, z1.x, z1.y);
        *(float4*)&Zf[l * ZSTRIDE + 256 + tx * 4] = make_float4(z2.x, z2.y, z3.x, z3.y);
    }
    __syncthreads();

    {
        float p = d_probs[t];
        int nd = tid >> 3;
        int j0 = (tid & 7) * 16;
        int node = node0 + nd;
        int gbase = node * FOUT + j0;
#pragma unroll
        for (int q = 0; q < 4; q++) {
            float4 c4 = *(const float4*)&d_C[gbase + q * 4];
            float4 a4 = (t == 0) ? make_float4(0.f, 0.f, 0.f, 0.f)
                                 : *(const float4*)&Hacc[gbase + q * 4];
            float hv[4], cv[4], av4[4];
            const float* cold = &c4.x;
            const float* aold = &a4.x;
#pragma unroll
            for (int u = 0; u < 4; u++) {
                int j = j0 + q * 4 + u;
                float zi = Zf[nd * ZSTRIDE + j]       + d_bias[j];
                float zf = Zf[nd * ZSTRIDE + 128 + j] + d_bias[128 + j];
                float zc = Zf[nd * ZSTRIDE + 256 + j] + d_bias[256 + j];
                float zo = Zf[nd * ZSTRIDE + 384 + j] + d_bias[384 + j];
                float I  = 1.f / (1.f + __expf(-zi));
                float F  = 1.f / (1.f + __expf(-zf));
                float Ct = 1.f - 2.f / (__expf(2.f * zc) + 1.f);
                float O  = 1.f / (1.f + __expf(-zo));
                float cn = F * cold[u] + I * Ct;
                float hh = O * (1.f - 2.f / (__expf(2.f * cn) + 1.f));
                hv[u] = hh; cv[u] = cn; av4[u] = aold[u] + p * hh;
            }
            *(float4*)&d_H[gbase + q * 4]  = make_float4(hv[0], hv[1], hv[2], hv[3]);
            *(float4*)&d_C[gbase + q * 4]  = make_float4(cv[0], cv[1], cv[2], cv[3]);
            *(float4*)&Hacc[gbase + q * 4] = make_float4(av4[0], av4[1], av4[2], av4[3]);
        }
    }
}

// ---------------- launch ----------------
extern "C" void kernel_launch(void* const* d_in, const int* in_sizes, int n_in,
                              void* d_out, int out_size) {
    const float* X   = (const float*)d_in[0];
    const int*   ei  = (const int*)d_in[1];
    const float* ew  = (const float*)d_in[2];
    const float* att = (const float*)d_in[3];
    GateW gw;
    for (int g = 0; g < 4; g++) {
        gw.wx[g] = (const float*)d_in[4 + 4 * g];
        gw.bx[g] = (const float*)d_in[5 + 4 * g];
        gw.wh[g] = (const float*)d_in[6 + 4 * g];
        gw.bh[g] = (const float*)d_in[7 + 4 * g];
    }
    gw.att = att;
    float* out = (float*)d_out;

    // lazy one-time resources (created on the uncaptured correctness call,
    // reused identically during capture; work per call is identical)
    static cudaStream_t s2 = 0;
    static cudaEvent_t eFork = 0, eS[NP];
    if (!s2) {
        cudaStreamCreateWithFlags(&s2, cudaStreamNonBlocking);
        cudaEventCreateWithFlags(&eFork, cudaEventDisableTiming);
        for (int t = 1; t < NP; t++)
            cudaEventCreateWithFlags(&eS[t], cudaEventDisableTiming);
        cudaFuncSetAttribute(step_ffma_kernel, cudaFuncAttributeMaxDynamicSharedMemorySize, SMEM_TOT);
    }

    // serial prologue (stream 0)
    zero_kernel<<<512, 256>>>();
    deg_kernel<<<640, 256>>>(ei, ew);
    scan_kernel<<<1, 1024>>>();
    fill_kernel<<<640, 256>>>(ei, ew);
    prep_kernel<<<193, 512>>>(gw);
    transpose_kernel<<<NN, 768>>>(X);

    // fork: spmm for t=1..11 runs on s2, overlapping the step chain
    cudaEventRecord(eFork, 0);
    cudaStreamWaitEvent(s2, eFork, 0);
    for (int t = 1; t < NP; t++) {
        spmm_t_kernel<<<NN / 4, 256, 0, s2>>>(t);
        cudaEventRecord(eS[t], s2);
    }

    // main chain: spmm(0) then steps, each step waiting on its S slice
    spmm_t_kernel<<<NN / 4, 256>>>(0);
    step_ffma_kernel<<<NN / BN, 256, SMEM_TOT>>>(0, out);
    for (int t = 1; t < NP; t++) {
        cudaStreamWaitEvent(0, eS[t], 0);
        step_ffma_kernel<<<NN / BN, 256, SMEM_TOT>>>(t, out);
    }
}

// round 13
// speedup vs baseline: 1.2955x; 1.0366x over previous
#include <cuda_runtime.h>
#include <math.h>
#include <stdint.h>

#define NN   40000
#define NE   640000
#define FIN  64
#define FOUT 128
#define NP   12
#define FTOT 768
#define GC   512      /* 4*FOUT */
#define KTOT 192
#define BN   32       /* nodes per fused CTA */

// ---------------- device scratch ----------------
__device__ float d_deg[NN];
__device__ float d_dinv[NN];
__device__ int   d_counts[NN];
__device__ int   d_cursor[NN];
__device__ int   d_offsets[NN + 1];
__device__ int   d_csr[NE];       // source node per CSR slot
__device__ float d_csrw[NE];      // norm weight per CSR slot
__device__ float d_Xt[(size_t)NP * NN * FIN];  // X transposed [t][n][f]
__device__ float d_S[(size_t)NP * NN * FIN];   // [t][n][f]
__device__ float d_W1[FIN * GC];               // folded W_x @ W_h_top
__device__ float d_W2[FOUT * GC];              // W_h_bottom
__device__ float d_bias[GC];
__device__ float d_probs[NP];

struct GateW {
    const float* wx[4];
    const float* bx[4];
    const float* wh[4];
    const float* bh[4];
    const float* att;
};

// ---------------- packed f32x2 helpers ----------------
__device__ __forceinline__ unsigned long long pk2(float x) {
    unsigned long long r;
    asm("mov.b64 %0, {%1, %1};" : "=l"(r) : "f"(x));
    return r;
}
__device__ __forceinline__ unsigned long long f2fma(unsigned long long a,
                                                    unsigned long long b,
                                                    unsigned long long c) {
    unsigned long long d;
    asm("fma.rn.f32x2 %0, %1, %2, %3;" : "=l"(d) : "l"(a), "l"(b), "l"(c));
    return d;
}
__device__ __forceinline__ float2 up2(unsigned long long v) {
    float2 r;
    asm("mov.b64 {%0, %1}, %2;" : "=f"(r.x), "=f"(r.y) : "l"(v));
    return r;
}

// ---------------- async copy helpers ----------------
__device__ __forceinline__ uint32_t smem_u32(const void* p) {
    uint32_t a;
    asm("{ .reg .u64 t; cvta.to.shared.u64 t, %1; cvt.u32.u64 %0, t; }" : "=r"(a) : "l"(p));
    return a;
}
__device__ __forceinline__ void cp16(uint32_t dst, const void* src) {
    asm volatile("cp.async.cg.shared.global [%0], [%1], 16;" :: "r"(dst), "l"(src));
}
#define CP_COMMIT() asm volatile("cp.async.commit_group;" ::: "memory")
#define CP_WAIT(n)  asm volatile("cp.async.wait_group %0;" :: "n"(n) : "memory")

// ---------------- small kernels ----------------
__global__ void zero_kernel() {
    int i = blockIdx.x * blockDim.x + threadIdx.x;
    int stride = gridDim.x * blockDim.x;
    for (int idx = i; idx < NN; idx += stride) { d_deg[idx] = 0.f; d_counts[idx] = 0; d_cursor[idx] = 0; }
}

__global__ void deg_kernel(const int* __restrict__ ei, const float* __restrict__ ew) {
    int i = blockIdx.x * blockDim.x + threadIdx.x;
    int stride = gridDim.x * blockDim.x;
    for (int e = i; e < NE; e += stride) {
        int c = ei[NE + e];
        atomicAdd(&d_deg[c], ew[e]);
        atomicAdd(&d_counts[c], 1);
    }
}

__global__ __launch_bounds__(1024) void scan_kernel() {
    int tid = threadIdx.x;
    for (int n = tid; n < NN; n += 1024)
        d_dinv[n] = rsqrtf(d_deg[n] + 1.0f);
    const int CH = 40;
    int base = tid * CH;
    int sum = 0;
#pragma unroll 4
    for (int i = 0; i < CH; i++) { int idx = base + i; if (idx < NN) sum += d_counts[idx]; }
    int lane = tid & 31, wid = tid >> 5;
    int v = sum;
#pragma unroll
    for (int o = 1; o < 32; o <<= 1) { int t = __shfl_up_sync(0xffffffffu, v, o); if (lane >= o) v += t; }
    __shared__ int wsum[32];
    if (lane == 31) wsum[wid] = v;
    __syncthreads();
    if (wid == 0) {
        int w = wsum[lane];
#pragma unroll
        for (int o = 1; o < 32; o <<= 1) { int t = __shfl_up_sync(0xffffffffu, w, o); if (lane >= o) w += t; }
        wsum[lane] = w;
    }
    __syncthreads();
    int excl = v - sum + (wid ? wsum[wid - 1] : 0);
    int run = excl;
#pragma unroll 4
    for (int i = 0; i < CH; i++) {
        int idx = base + i;
        if (idx < NN) { d_offsets[idx] = run; run += d_counts[idx]; }
    }
    if (tid == 1023) d_offsets[NN] = run;
}

__global__ void fill_kernel(const int* __restrict__ ei, const float* __restrict__ ew) {
    int i = blockIdx.x * blockDim.x + threadIdx.x;
    int stride = gridDim.x * blockDim.x;
    for (int e = i; e < NE; e += stride) {
        int c = ei[NE + e];
        int r = ei[e];
        int p = atomicAdd(&d_cursor[c], 1);
        int slot = d_offsets[c] + p;
        d_csr[slot]  = r;
        d_csrw[slot] = d_dinv[r] * ew[e] * d_dinv[c];
    }
}

__global__ __launch_bounds__(512) void prep_kernel(GateW gw) {
    int b = blockIdx.x;
    int c = threadIdx.x;
    int g = c >> 7, j = c & 127;
    if (b < 64) {
        int k = b;
        const float* wx = gw.wx[g];
        const float* wh = gw.wh[g];
        float acc = 0.f;
#pragma unroll 8
        for (int m = 0; m < FOUT; m++) acc += wx[k * FOUT + m] * wh[m * FOUT + j];
        d_W1[k * GC + c] = acc;
    } else if (b < 192) {
        int k = b - 64;
        d_W2[k * GC + c] = gw.wh[g][(FOUT + k) * FOUT + j];
    } else {
        float acc = gw.bh[g][j];
        for (int m = 0; m < FOUT; m++) acc += gw.bx[g][m] * gw.wh[g][m * FOUT + j];
        d_bias[c] = acc;
        if (c == 0) {
            float a[NP], mx = -1e30f, s = 0.f;
            for (int t = 0; t < NP; t++) { a[t] = gw.att[t]; mx = fmaxf(mx, a[t]); }
            for (int t = 0; t < NP; t++) { a[t] = expf(a[t] - mx); s += a[t]; }
            for (int t = 0; t < NP; t++) d_probs[t] = a[t] / s;
        }
    }
}

// X [n][f][t] -> Xt [t][n][f]
__global__ __launch_bounds__(768) void transpose_kernel(const float* __restrict__ X) {
    __shared__ float sv[FTOT];
    int n = blockIdx.x;
    int tid = threadIdx.x;
    sv[tid] = X[(size_t)n * FTOT + tid];
    __syncthreads();
    int t = tid >> 6, f = tid & 63;
    d_Xt[((size_t)t * NN + n) * FIN + f] = sv[f * NP + t];
}

// all-period gather SpMM: grid (NN/4, NP)
__global__ __launch_bounds__(256) void spmm_all_kernel() {
    int t = blockIdx.y;
    int nd = blockIdx.x * 4 + (threadIdx.x >> 6);
    int f = threadIdx.x & 63;
    const float* Xt = d_Xt + (size_t)t * NN * FIN;
    float dn = d_dinv[nd];
    float acc = dn * dn * Xt[(size_t)nd * FIN + f];
    int beg = d_offsets[nd], end = d_offsets[nd + 1];
    int e = beg;
    float acc2 = 0.f;
    for (; e + 1 < end; e += 2) {
        acc  += d_csrw[e]     * Xt[(size_t)d_csr[e] * FIN + f];
        acc2 += d_csrw[e + 1] * Xt[(size_t)d_csr[e + 1] * FIN + f];
    }
    if (e < end) acc += d_csrw[e] * Xt[(size_t)d_csr[e] * FIN + f];
    __stcs(&d_S[((size_t)t * NN + nd) * FIN + f], acc + acc2);
}

// ---------------- fused 12-step FFMA2 kernel (2 CTAs/SM) ----------------
// CTA: 32 nodes, 256 threads, loops t=0..11 internally.
// Thread cols: {j, 128+j, 256+j, 384+j} for j = (tid&63)*2 (+1) -> epilogue local.
// H, C in SMEM for all steps; Hacc in regs, written once.
#define SM_B     0                       /* 2 x 32KB B chunk buffers */
#define SM_SA    65536                   /* 2 x 2KB S-part A buffers */
#define SM_H     (65536 + 4096)          /* 69632: 32 x 132 floats   */
#define SM_C     (69632 + 16896)         /* 86528: 32 x 132 floats   */
#define SMEM_TOT (86528 + 16896)         /* 103424 */
#define HSTRIDE  132

__device__ __forceinline__ void issue_chunk(uint32_t sb, int g, int node0, int tid) {
    int t = g / 12, c = g % 12;
    if (c < 4 && tid < 128) {
        int row = tid >> 2, q = tid & 3;
        int node = node0 + row;
        const float* src = &d_S[(size_t)t * NN * FIN + (size_t)node * FIN + c * 16 + q * 4];
        cp16(sb + SM_SA + ((t * 4 + c) & 1) * 2048 + row * 64 + q * 16, src);
    }
#pragma unroll
    for (int i = 0; i < 8; i++) {
        int op = tid + 256 * i;            // 0..2047
        int row = op >> 7, q = op & 127;
        const float* src = (c < 4) ? &d_W1[(c * 16 + row) * GC + q * 4]
                                   : &d_W2[((c - 4) * 16 + row) * GC + q * 4];
        cp16(sb + SM_B + (g & 1) * 32768 + row * 2048 + q * 16, src);
    }
}

__global__ __launch_bounds__(256, 2) void fused_steps_kernel(float* __restrict__ Hacc_g) {
    extern __shared__ char smem[];
    uint32_t sb = smem_u32(smem);
    int tid = threadIdx.x;
    int tx = tid & 63;        // col pair j = tx*2
    int ty = tid >> 6;        // node group (0..3): nodes ty*8..ty*8+7
    int node0 = blockIdx.x * BN;
    float* Hs = (float*)(smem + SM_H);
    float* Cs = (float*)(smem + SM_C);

    for (int i = tid; i < BN * HSTRIDE; i += 256) { Hs[i] = 0.f; Cs[i] = 0.f; }

    float2 Ha[8];
#pragma unroll
    for (int i = 0; i < 8; i++) Ha[i] = make_float2(0.f, 0.f);

    float2 bI = *(const float2*)&d_bias[tx * 2];
    float2 bF = *(const float2*)&d_bias[128 + tx * 2];
    float2 bC = *(const float2*)&d_bias[256 + tx * 2];
    float2 bO = *(const float2*)&d_bias[384 + tx * 2];

    __syncthreads();

    issue_chunk(sb, 0, node0, tid);
    CP_COMMIT();

    for (int t = 0; t < NP; t++) {
        unsigned long long acc[8][4];
#pragma unroll
        for (int i = 0; i < 8; i++)
#pragma unroll
            for (int j = 0; j < 4; j++) acc[i][j] = 0ull;

        for (int c = 0; c < 12; c++) {
            int g = t * 12 + c;
            if (g < NP * 12 - 1) {
                issue_chunk(sb, g + 1, node0, tid);
                CP_COMMIT();
                CP_WAIT(1);
            } else {
                CP_WAIT(0);
            }
            __syncthreads();

            const unsigned long long* Bu =
                (const unsigned long long*)(smem + SM_B + (g & 1) * 32768);

            if (c < 4) {
                const float2* Af2 = (const float2*)(smem + SM_SA + ((t * 4 + c) & 1) * 2048);
#pragma unroll
                for (int kg = 0; kg < 8; kg++) {
                    float2 av[8];
#pragma unroll
                    for (int i = 0; i < 8; i++) av[i] = Af2[(ty * 8 + i) * 8 + kg];
#pragma unroll
                    for (int k2 = 0; k2 < 2; k2++) {
                        const unsigned long long* Bk = Bu + (kg * 2 + k2) * 256;
                        unsigned long long bb0 = Bk[tx];
                        unsigned long long bb1 = Bk[64 + tx];
                        unsigned long long bb2 = Bk[128 + tx];
                        unsigned long long bb3 = Bk[192 + tx];
#pragma unroll
                        for (int i = 0; i < 8; i++) {
                            unsigned long long aa = pk2(k2 ? av[i].y : av[i].x);
                            acc[i][0] = f2fma(aa, bb0, acc[i][0]);
                            acc[i][1] = f2fma(aa, bb1, acc[i][1]);
                            acc[i][2] = f2fma(aa, bb2, acc[i][2]);
                            acc[i][3] = f2fma(aa, bb3, acc[i][3]);
                        }
                    }
                }
            } else {
                int k0 = (c - 4) * 16;
#pragma unroll
                for (int kg = 0; kg < 8; kg++) {
                    float2 av[8];
#pragma unroll
                    for (int i = 0; i < 8; i++)
                        av[i] = *(const float2*)&Hs[(ty * 8 + i) * HSTRIDE + k0 + kg * 2];
#pragma unroll
                    for (int k2 = 0; k2 < 2; k2++) {
                        const unsigned long long* Bk = Bu + (kg * 2 + k2) * 256;
                        unsigned long long bb0 = Bk[tx];
                        unsigned long long bb1 = Bk[64 + tx];
                        unsigned long long bb2 = Bk[128 + tx];
                        unsigned long long bb3 = Bk[192 + tx];
#pragma unroll
                        for (int i = 0; i < 8; i++) {
                            unsigned long long aa = pk2(k2 ? av[i].y : av[i].x);
                            acc[i][0] = f2fma(aa, bb0, acc[i][0]);
                            acc[i][1] = f2fma(aa, bb1, acc[i][1]);
                            acc[i][2] = f2fma(aa, bb2, acc[i][2]);
                            acc[i][3] = f2fma(aa, bb3, acc[i][3]);
                        }
                    }
                }
            }
            __syncthreads();
        }

        // ---- thread-local LSTM epilogue ----
        float p = d_probs[t];
#pragma unroll
        for (int i = 0; i < 8; i++) {
            int nd = ty * 8 + i;
            float2 zI = up2(acc[i][0]);
            float2 zF = up2(acc[i][1]);
            float2 zC = up2(acc[i][2]);
            float2 zO = up2(acc[i][3]);
            float2 cold = *(const float2*)&Cs[nd * HSTRIDE + tx * 2];
            float I0 = 1.f / (1.f + __expf(-(zI.x + bI.x)));
            float F0 = 1.f / (1.f + __expf(-(zF.x + bF.x)));
            float T0 = 1.f - 2.f / (__expf(2.f * (zC.x + bC.x)) + 1.f);
            float O0 = 1.f / (1.f + __expf(-(zO.x + bO.x)));
            float cn0 = F0 * cold.x + I0 * T0;
            float hh0 = O0 * (1.f - 2.f / (__expf(2.f * cn0) + 1.f));
            float I1 = 1.f / (1.f + __expf(-(zI.y + bI.y)));
            float F1 = 1.f / (1.f + __expf(-(zF.y + bF.y)));
            float T1 = 1.f - 2.f / (__expf(2.f * (zC.y + bC.y)) + 1.f);
            float O1 = 1.f / (1.f + __expf(-(zO.y + bO.y)));
            float cn1 = F1 * cold.y + I1 * T1;
            float hh1 = O1 * (1.f - 2.f / (__expf(2.f * cn1) + 1.f));
            *(float2*)&Cs[nd * HSTRIDE + tx * 2] = make_float2(cn0, cn1);
            *(float2*)&Hs[nd * HSTRIDE + tx * 2] = make_float2(hh0, hh1);
            Ha[i].x += p * hh0;
            Ha[i].y += p * hh1;
        }
        __syncthreads();   // H visible before next step's k>=64 chunks
    }

    // ---- final Hacc writeback ----
#pragma unroll
    for (int i = 0; i < 8; i++) {
        int node = node0 + ty * 8 + i;
        *(float2*)&Hacc_g[node * FOUT + tx * 2] = Ha[i];
    }
}

// ---------------- launch ----------------
extern "C" void kernel_launch(void* const* d_in, const int* in_sizes, int n_in,
                              void* d_out, int out_size) {
    const float* X   = (const float*)d_in[0];
    const int*   ei  = (const int*)d_in[1];
    const float* ew  = (const float*)d_in[2];
    const float* att = (const float*)d_in[3];
    GateW gw;
    for (int g = 0; g < 4; g++) {
        gw.wx[g] = (const float*)d_in[4 + 4 * g];
        gw.bx[g] = (const float*)d_in[5 + 4 * g];
        gw.wh[g] = (const float*)d_in[6 + 4 * g];
        gw.bh[g] = (const float*)d_in[7 + 4 * g];
    }
    gw.att = att;
    float* out = (float*)d_out;

    cudaFuncSetAttribute(fused_steps_kernel, cudaFuncAttributeMaxDynamicSharedMemorySize, SMEM_TOT);

    zero_kernel<<<160, 256>>>();
    deg_kernel<<<640, 256>>>(ei, ew);
    scan_kernel<<<1, 1024>>>();
    fill_kernel<<<640, 256>>>(ei, ew);
    prep_kernel<<<193, 512>>>(gw);
    transpose_kernel<<<NN, 768>>>(X);
    spmm_all_kernel<<<dim3(NN / 4, NP), 256>>>();
    fused_steps_kernel<<<NN / BN, 256, SMEM_TOT>>>(out);
}